// round 12
// baseline (speedup 1.0000x reference)
#include <cuda_runtime.h>
#include <cuda_bf16.h>
#include <cuda_fp16.h>
#include <math.h>

#define MAXN 100000
#define MAXE 1600000
#define HDIM 64
#define NB   512          // k_scanfill grid size (co-resident by launch_bounds)

// ---------------- scratch (static device globals; no allocation) -------------
__device__ int      g_counts [MAXN];
__device__ int      g_offsets[MAXN];
__device__ int      g_cursor [MAXN];
__device__ float    g_dis    [MAXN];
__device__ float2   g_epack  [MAXE];      // .x = __int_as_float(src), .y = norm
__device__ float    g_h  [2][MAXN * HDIM];         // fp32 features, ping-pong
__device__ __half2  g_hh [2][MAXN * (HDIM / 2)];   // fp16 features, ping-pong
__device__ int      g_bsum   [NB];
__device__ int      g_is64;               // 1 if edge_index is int64, 0 if int32
__device__ unsigned g_bar_count   = 0;    // grid barrier: arrive counter
__device__ unsigned g_bar_release = 0;    // grid barrier: monotonic epoch

// ---------------- zero + dtype probe + x->fp16 copy (into hh[0]) -------------
__global__ void k_zero_probe_x2h(const void* __restrict__ ei_raw,
                                 const float* __restrict__ x, int n) {
    int i = blockIdx.x * blockDim.x + threadIdx.x;
    int n32 = n * 32;
    if (i < n32) {
        float2 v = ((const float2*)x)[i];
        g_hh[0][i] = __float22half2_rn(v);
    }
    if (i < n) g_counts[i] = 0;
    if (i == 0) {
        const long long* e64 = (const long long*)ei_raw;
        int ok64 = 1;
        for (int k = 0; k < 8; k++) {
            long long v = e64[k];
            if (v < 0 || v >= (long long)n) ok64 = 0;
        }
        g_is64 = ok64;
    }
}

// ---------------- count in-degrees (vectorized: 2 edges/thread) --------------
__global__ void k_count(const void* __restrict__ ei_raw, int e, int n) {
    int i = blockIdx.x * blockDim.x + threadIdx.x;   // pair index
    if (2 * i >= e) return;
    int d0, d1;
    if (g_is64) {
        const longlong2* p = (const longlong2*)((const long long*)ei_raw + e);
        longlong2 v = __ldg(&p[i]);
        d0 = (int)v.x; d1 = (int)v.y;
    } else {
        const int2* p = (const int2*)((const int*)ei_raw + e);
        int2 v = __ldg(&p[i]);
        d0 = v.x; d1 = v.y;
    }
    if ((unsigned)d0 < (unsigned)n) atomicAdd(&g_counts[d0], 1);
    if ((unsigned)d1 < (unsigned)n) atomicAdd(&g_counts[d1], 1);
}

// ---------------- fused scan + fill (cooperative, grid barrier) --------------
// Phase A: exclusive scan of counts -> offsets/cursor + dis = rsqrt(deg+1)
// Phase B: fill CSR (packed src+norm), grid-stride over edge pairs.
// Grid barrier: monotonic-epoch (state at rest after each call). launch_bounds
// (256, 4) guarantees >= 4 blocks/SM co-residency; NB=512 <= 4*148.
__global__ void __launch_bounds__(256, 4)
k_scanfill(const void* __restrict__ ei_raw, int e, int n) {
    __shared__ int ss[256];

    const int t  = threadIdx.x;
    const int b  = blockIdx.x;
    const int T  = NB * 256;
    const int gt = b * 256 + t;

    unsigned base = 0;
    int nbar = 0;
    if (t == 0) base = *(volatile unsigned*)&g_bar_release;

    auto gsync = [&]() {
        __threadfence();
        __syncthreads();
        if (t == 0) {
            nbar++;
            unsigned arr = atomicAdd(&g_bar_count, 1u);
            if (arr == (unsigned)NB - 1u) {
                atomicExch(&g_bar_count, 0u);
                __threadfence();
                atomicAdd(&g_bar_release, 1u);
            }
            while (*(volatile unsigned*)&g_bar_release < base + (unsigned)nbar) { }
        }
        __syncthreads();
    };

    // ---- phase A1: per-thread sums + block scan -> block totals ----
    const int lenN = (n + T - 1) / T;      // == 1 for n <= 131072
    const int lo = gt * lenN;
    const int hi = min(lo + lenN, n);
    int mysum = 0;
    for (int i = lo; i < hi; i++) mysum += g_counts[i];

    ss[t] = mysum;
    __syncthreads();
#pragma unroll
    for (int off = 1; off < 256; off <<= 1) {
        int v = (t >= off) ? ss[t - off] : 0;
        __syncthreads();
        ss[t] += v;
        __syncthreads();
    }
    const int thr_excl = ss[t] - mysum;    // exclusive prefix within block
    if (t == 255) g_bsum[b] = ss[255];
    gsync();

    // ---- phase A2: block base = sum of totals of blocks < b ----
    {
        int partial = 0;
        for (int j = t; j < NB; j += 256)
            if (j < b) partial += g_bsum[j];
        __syncthreads();                   // ss reuse
        ss[t] = partial;
        __syncthreads();
#pragma unroll
        for (int off = 128; off > 0; off >>= 1) {
            if (t < off) ss[t] += ss[t + off];
            __syncthreads();
        }
        const int block_base = ss[0];
        int off = block_base + thr_excl;
        for (int i = lo; i < hi; i++) {
            int c = g_counts[i];
            g_offsets[i] = off;
            g_cursor[i]  = off;
            g_dis[i]     = rsqrtf((float)(c + 1));
            off += c;
        }
    }
    gsync();

    // ---- phase B: fill CSR (grid-stride over edge pairs) ----
    const int pairs = e / 2;
    if (g_is64) {
        const longlong2* ps = (const longlong2*)((const long long*)ei_raw);
        const longlong2* pd = (const longlong2*)((const long long*)ei_raw + e);
        for (int i = gt; i < pairs; i += T) {
            longlong2 vs = __ldg(&ps[i]);
            longlong2 vd = __ldg(&pd[i]);
            int s0 = (int)vs.x, s1 = (int)vs.y;
            int d0 = (int)vd.x, d1 = (int)vd.y;
            if ((unsigned)s0 < (unsigned)n && (unsigned)d0 < (unsigned)n) {
                int p = atomicAdd(&g_cursor[d0], 1);
                g_epack[p] = make_float2(__int_as_float(s0), g_dis[s0] * g_dis[d0]);
            }
            if ((unsigned)s1 < (unsigned)n && (unsigned)d1 < (unsigned)n) {
                int p = atomicAdd(&g_cursor[d1], 1);
                g_epack[p] = make_float2(__int_as_float(s1), g_dis[s1] * g_dis[d1]);
            }
        }
    } else {
        const int2* ps = (const int2*)((const int*)ei_raw);
        const int2* pd = (const int2*)((const int*)ei_raw + e);
        for (int i = gt; i < pairs; i += T) {
            int2 vs = __ldg(&ps[i]);
            int2 vd = __ldg(&pd[i]);
            int s0 = vs.x, s1 = vs.y, d0 = vd.x, d1 = vd.y;
            if ((unsigned)s0 < (unsigned)n && (unsigned)d0 < (unsigned)n) {
                int p = atomicAdd(&g_cursor[d0], 1);
                g_epack[p] = make_float2(__int_as_float(s0), g_dis[s0] * g_dis[d0]);
            }
            if ((unsigned)s1 < (unsigned)n && (unsigned)d1 < (unsigned)n) {
                int p = atomicAdd(&g_cursor[d1], 1);
                g_epack[p] = make_float2(__int_as_float(s1), g_dis[s1] * g_dis[d1]);
            }
        }
    }
}

// ---------------- fused layer: out = [relu]( (A_hat @ in) @ W + b ) ----------
// One block = 64 dst nodes, 256 threads. PING-PONG buffers: read set
// (h[h_in] or x, hh[hh_in]) and write set (h[h_out], hh[hh_out] or d_out) are
// disjoint in every launch -> no cross-block read/write race.
__global__ void k_layer(const float* __restrict__ xin,
                        const float* __restrict__ W, const float* __restrict__ b,
                        float* __restrict__ outp,
                        int n, int do_relu, int to_out, int from_x,
                        int h_in, int hh_in, int h_out, int hh_out) {
    __shared__ float Ws[64 * 64];
    __shared__ float xs[64 * 68];   // transposed tile: xs[k*68 + r]

    const int t    = threadIdx.x;
    const int wid  = t >> 5;
    const int lane = t & 31;
    const int row0 = blockIdx.x * 64;

    for (int i = t; i < 4096; i += 256) Ws[i] = W[i];

    const float2* __restrict__ selfsrc =
        (const float2*)(from_x ? xin : (const float*)g_h[h_in]);
    const __half2* __restrict__ hin = (const __half2*)g_hh[hh_in];

    // ---- phase 1: aggregate 8 nodes per warp ----
#pragma unroll 1
    for (int rr = 0; rr < 8; rr++) {
        const int r    = wid * 8 + rr;     // local row
        const int node = row0 + r;
        float acc0 = 0.f, acc1 = 0.f;
        if (node < n) {
            float di    = g_dis[node];
            float selfc = di * di;
            float2 sv = __ldg(&selfsrc[(size_t)node * 32 + lane]);
            acc0 = sv.x * selfc;
            acc1 = sv.y * selfc;

            int start = g_offsets[node];
            int cnt   = g_counts[node];
            int j = 0;
            for (; j + 4 <= cnt; j += 4) {
                float2 m0 = __ldg(&g_epack[start + j]);
                float2 m1 = __ldg(&g_epack[start + j + 1]);
                float2 m2 = __ldg(&g_epack[start + j + 2]);
                float2 m3 = __ldg(&g_epack[start + j + 3]);
                __half2 h0 = __ldg(&hin[(size_t)__float_as_int(m0.x) * 32 + lane]);
                __half2 h1 = __ldg(&hin[(size_t)__float_as_int(m1.x) * 32 + lane]);
                __half2 h2 = __ldg(&hin[(size_t)__float_as_int(m2.x) * 32 + lane]);
                __half2 h3 = __ldg(&hin[(size_t)__float_as_int(m3.x) * 32 + lane]);
                float2 f0 = __half22float2(h0);
                float2 f1 = __half22float2(h1);
                float2 f2 = __half22float2(h2);
                float2 f3 = __half22float2(h3);
                acc0 = fmaf(m0.y, f0.x, acc0);  acc1 = fmaf(m0.y, f0.y, acc1);
                acc0 = fmaf(m1.y, f1.x, acc0);  acc1 = fmaf(m1.y, f1.y, acc1);
                acc0 = fmaf(m2.y, f2.x, acc0);  acc1 = fmaf(m2.y, f2.y, acc1);
                acc0 = fmaf(m3.y, f3.x, acc0);  acc1 = fmaf(m3.y, f3.y, acc1);
            }
            for (; j < cnt; j++) {
                float2 m = __ldg(&g_epack[start + j]);
                __half2 h = __ldg(&hin[(size_t)__float_as_int(m.x) * 32 + lane]);
                float2 f = __half22float2(h);
                acc0 = fmaf(m.y, f.x, acc0);
                acc1 = fmaf(m.y, f.y, acc1);
            }
        }
        xs[(2 * lane)     * 68 + r] = acc0;
        xs[(2 * lane + 1) * 68 + r] = acc1;
    }
    __syncthreads();

    // ---- phase 2: GEMM 64x64 ----
    float* __restrict__ out = to_out ? outp : (float*)g_h[h_out];
    const int tx = t & 15, ty = t >> 4;
    const int c0 = tx * 4, r0 = ty * 4;

    float acc[4][4] = {};
#pragma unroll
    for (int k = 0; k < 64; k++) {
        float4 xv = *(const float4*)&xs[k * 68 + r0];
        float4 wv = *(const float4*)&Ws[k * 64 + c0];
        acc[0][0] = fmaf(xv.x, wv.x, acc[0][0]);
        acc[0][1] = fmaf(xv.x, wv.y, acc[0][1]);
        acc[0][2] = fmaf(xv.x, wv.z, acc[0][2]);
        acc[0][3] = fmaf(xv.x, wv.w, acc[0][3]);
        acc[1][0] = fmaf(xv.y, wv.x, acc[1][0]);
        acc[1][1] = fmaf(xv.y, wv.y, acc[1][1]);
        acc[1][2] = fmaf(xv.y, wv.z, acc[1][2]);
        acc[1][3] = fmaf(xv.y, wv.w, acc[1][3]);
        acc[2][0] = fmaf(xv.z, wv.x, acc[2][0]);
        acc[2][1] = fmaf(xv.z, wv.y, acc[2][1]);
        acc[2][2] = fmaf(xv.z, wv.z, acc[2][2]);
        acc[2][3] = fmaf(xv.z, wv.w, acc[2][3]);
        acc[3][0] = fmaf(xv.w, wv.x, acc[3][0]);
        acc[3][1] = fmaf(xv.w, wv.y, acc[3][1]);
        acc[3][2] = fmaf(xv.w, wv.z, acc[3][2]);
        acc[3][3] = fmaf(xv.w, wv.w, acc[3][3]);
    }

    float4 bv = *(const float4*)&b[c0];
#pragma unroll
    for (int rr = 0; rr < 4; rr++) {
        int r = row0 + r0 + rr;
        if (r < n) {
            float4 o;
            o.x = acc[rr][0] + bv.x;
            o.y = acc[rr][1] + bv.y;
            o.z = acc[rr][2] + bv.z;
            o.w = acc[rr][3] + bv.w;
            if (do_relu) {
                o.x = fmaxf(o.x, 0.0f);
                o.y = fmaxf(o.y, 0.0f);
                o.z = fmaxf(o.z, 0.0f);
                o.w = fmaxf(o.w, 0.0f);
            }
            *(float4*)&out[(size_t)r * HDIM + c0] = o;
            if (!to_out) {                 // fp16 copy for next layer's gathers
                union { __half2 h[2]; uint2 u; } cv;
                cv.h[0] = __float22half2_rn(make_float2(o.x, o.y));
                cv.h[1] = __float22half2_rn(make_float2(o.z, o.w));
                *(uint2*)&g_hh[hh_out][(size_t)r * 32 + (c0 >> 1)] = cv.u;
            }
        }
    }
}

// ---------------- launch ------------------------------------------------------
extern "C" void kernel_launch(void* const* d_in, const int* in_sizes, int n_in,
                              void* d_out, int out_size) {
    const float* x  = (const float*)d_in[0];
    const void*  ei = d_in[1];
    // d_in[2] = edge_features (unused by GCNConv reference)
    const float* W1 = (const float*)d_in[3];
    const float* b1 = (const float*)d_in[4];
    const float* W2 = (const float*)d_in[5];
    const float* b2 = (const float*)d_in[6];
    const float* W3 = (const float*)d_in[7];
    const float* b3 = (const float*)d_in[8];
    float* outp = (float*)d_out;

    int N = in_sizes[0] / HDIM;
    int E = in_sizes[1] / 2;
    int Ep = E / 2;                      // edge pairs (E is even)

    // ---- preprocessing: 3 launches ----
    k_zero_probe_x2h<<<(N * 32 + 255) / 256, 256>>>(ei, x, N);
    k_count<<<(Ep + 255) / 256, 256>>>(ei, E, N);
    k_scanfill<<<NB, 256>>>(ei, E, N);

    int layer_blocks = (N + 63) / 64;

    // ---- fused layers, ping-pong buffers (read/write sets disjoint) ----
    // L1: self=x,      gather hh[0] -> h[0], hh[1]   (launch index 3: profiled)
    // L2: self=h[0],   gather hh[1] -> h[1], hh[0]
    // L3: self=h[1],   gather hh[0] -> d_out
    k_layer<<<layer_blocks, 256>>>(x, W1, b1, outp, N, 1, 0, 1, 0, 0, 0, 1);
    k_layer<<<layer_blocks, 256>>>(x, W2, b2, outp, N, 1, 0, 0, 0, 1, 1, 0);
    k_layer<<<layer_blocks, 256>>>(x, W3, b3, outp, N, 0, 1, 0, 1, 0, 0, 0);
}